// round 11
// baseline (speedup 1.0000x reference)
#include <cuda_runtime.h>
#include <cstdint>

#define B_    16
#define T_    1024
#define V_    8192
#define H_    1024
#define NBLK  128
#define BTV   134217728   // B_*T_*V_

// ---------------------------------------------------------------------------
// Device-global scratch (allocation is forbidden) + grid-barrier state.
//   g_hs : [t][k][b] fp32 (GEMM A tiles; tile rows m = t*16+b)
//   g_hT : ping-pong h exchange in PAIR layout: idx = (j>>1)*32 + b*2 + (j&1)
// ---------------------------------------------------------------------------
__device__ float    g_hs[(size_t)T_ * B_ * H_];   // 64 MB
__device__ float    g_hT[2][B_ * H_];
__device__ unsigned g_bar_count = 0;
__device__ unsigned g_bar_sense = 0;

extern __shared__ float smem_dyn[];

// ---------------------------------------------------------------------------
// Packed f32x2 helpers (FFMA2 path: only reachable via PTX fma.rn.f32x2)
// ---------------------------------------------------------------------------
__device__ __forceinline__ unsigned long long pack2(float x, float y) {
    unsigned long long r;
    asm("mov.b64 %0, {%1, %2};" : "=l"(r) : "f"(x), "f"(y));
    return r;
}
__device__ __forceinline__ void fma2(unsigned long long &d,
                                     unsigned long long a,
                                     unsigned long long b) {
    asm("fma.rn.f32x2 %0, %1, %2, %0;" : "+l"(d) : "l"(a), "l"(b));
}
__device__ __forceinline__ void unpack2(unsigned long long v, float &lo, float &hi) {
    asm("mov.b64 {%0, %1}, %2;" : "=f"(lo), "=f"(hi) : "l"(v));
}

// ---------------------------------------------------------------------------
// Kernel 1: persistent RNN recurrence (exact verified R9 kernel).
//   h_t[b][j] = tanh( Wx_w[j, x[b,t]] + Wx_b[j] + sum_k h_{t-1}[b][k]*Wh[j][k] )
// 128 blocks x 128 threads; block owns 8 j, all 16 b.
// h held in PAIR layout [k/2][b][2] -> conflict-free LDS.64 + fma.f32x2.
// One flat grid barrier per step (sense-reversing; safe across graph replays).
// ---------------------------------------------------------------------------
__global__ void __launch_bounds__(128, 1)
rnn_recurrence_kernel(const int*   __restrict__ x,
                      const float* __restrict__ h0,
                      const float* __restrict__ Wx,
                      const float* __restrict__ Wxb,
                      const float* __restrict__ Wh,
                      float*       __restrict__ out,
                      int out_size)
{
    float* h_s  = smem_dyn;            // 16384 floats: h_{t-1} pair layout
    float* wh_s = smem_dyn + 16384;    //  8192 floats: Wh rows [jl][k]

    const int tid = threadIdx.x;
    const int j0  = (int)blockIdx.x * 8;
    const int jl  = tid >> 4;          // 0..7
    const int j   = j0 + jl;
    const int b   = tid & 15;

    {   // one-time: stage this block's 8 Wh rows (32 KB)
        const float4* src = (const float4*)(Wh + (size_t)j0 * H_);
        float4*       dst = (float4*)wh_s;
        #pragma unroll
        for (int s = 0; s < 16; s++)
            dst[tid + s * 128] = src[tid + s * 128];
    }

    const float  wxb   = Wxb[j];
    const float* wxrow = Wx + (size_t)j * V_;
    const int*   xrow  = x + b * T_;
    const float* whs   = wh_s + jl * H_;
    const int    pidx  = ((j >> 1) << 5) + (b << 1) + (j & 1);
    float*       hout  = g_hs + (size_t)j * 16 + b;    // [t][k][b], k = j

    for (int t = 0; t < T_; t++) {
        // ---- stage h_{t-1} into shared (pair layout) ----
        if (t == 0) {
            for (int i = tid; i < B_ * H_; i += 128) {
                int bb = (i >> 1) & 15;
                int kk = ((i >> 5) << 1) | (i & 1);
                h_s[i] = h0[bb * H_ + kk];
            }
        } else {
            const float4* src = (const float4*)(g_hT[(t - 1) & 1]);
            float4*       dst = (float4*)h_s;
            #pragma unroll
            for (int s = 0; s < 32; s++)
                dst[tid + s * 128] = __ldcg(src + tid + s * 128);
        }
        __syncthreads();

        // ---- embedding gather (L2-resident Wx) ----
        int   xi = __ldg(xrow + t);
        float e  = __ldg(wxrow + xi) + wxb;

        // ---- dot(h_{t-1}[b][:], Wh[j][:]) via f32x2, 8 chains ----
        unsigned long long acc2[8];
        #pragma unroll
        for (int i = 0; i < 8; i++) acc2[i] = 0ull;

        const char* hbase = (const char*)h_s + b * 8;
        #pragma unroll 2
        for (int kp = 0; kp < 512; kp += 8) {           // 16 k per iter
            ulonglong2 w01 = *(const ulonglong2*)(whs + 2 * kp);
            ulonglong2 w23 = *(const ulonglong2*)(whs + 2 * kp + 4);
            ulonglong2 w45 = *(const ulonglong2*)(whs + 2 * kp + 8);
            ulonglong2 w67 = *(const ulonglong2*)(whs + 2 * kp + 12);
            const char* hp = hbase + (size_t)kp * 128;
            fma2(acc2[0], *(const unsigned long long*)(hp + 0 * 128), w01.x);
            fma2(acc2[1], *(const unsigned long long*)(hp + 1 * 128), w01.y);
            fma2(acc2[2], *(const unsigned long long*)(hp + 2 * 128), w23.x);
            fma2(acc2[3], *(const unsigned long long*)(hp + 3 * 128), w23.y);
            fma2(acc2[4], *(const unsigned long long*)(hp + 4 * 128), w45.x);
            fma2(acc2[5], *(const unsigned long long*)(hp + 5 * 128), w45.y);
            fma2(acc2[6], *(const unsigned long long*)(hp + 6 * 128), w67.x);
            fma2(acc2[7], *(const unsigned long long*)(hp + 7 * 128), w67.y);
        }
        float dot;
        {
            float s0 = 0.f, s1 = 0.f;
            #pragma unroll
            for (int i = 0; i < 8; i += 2) {
                float l, h;
                unpack2(acc2[i], l, h);     s0 += l + h;
                unpack2(acc2[i + 1], l, h); s1 += l + h;
            }
            dot = s0 + s1;
        }
        float hv = tanhf(e + dot);

        // exchange buffer (pair layout; fully coalesced) + GEMM A matrix
        __stcg(&g_hT[t & 1][pidx], hv);
        __stcg(hout + (size_t)t * (B_ * H_), hv);

        if (t == T_ - 1 && out_size >= BTV + B_ * H_)
            out[(size_t)BTV + b * H_ + j] = hv;          // h_final [B][H]

        // ---- flat grid barrier (sense-reversing, replay-safe) ----
        __threadfence();
        __syncthreads();
        if (tid == 0) {
            unsigned gen = *((volatile unsigned*)&g_bar_sense);
            unsigned arr = atomicAdd(&g_bar_count, 1u);
            if (arr == NBLK - 1) {
                atomicExch(&g_bar_count, 0u);
                __threadfence();
                atomicAdd(&g_bar_sense, 1u);
            } else {
                while (*((volatile unsigned*)&g_bar_sense) == gen) { }
            }
        }
        __syncthreads();
        __threadfence();
    }
}

// ---------------------------------------------------------------------------
// Kernel 2: output GEMM (FFMA2), m-paired accumulators + duplicated-B smem.
//   logits[b][t][v] = sum_k hs[t][k][b] * Wy[v][k] + Wyb[v]
// A[m][k] = g_hs[t][k][b], m = t*16+b. 128x128x16 tiles, 256 threads.
// Inner loop: FFMA2 packs two adjacent m values, so A pairs load directly
// from As (LDS.128, no pack2), and B is stored pre-duplicated float2(b,b)
// so B pairs also load directly. Mix: 6 LDS + 32 FFMA2 per k (was 4+8+32).
// Accumulation chain per output is ordered identically to R9 -> same numerics.
// ---------------------------------------------------------------------------
#define BK    16
#define LDAS  132   // As row: 128 + pad 4 floats
#define LDBS  130   // Bs row: 128 + pad 2 float2 entries

__global__ void __launch_bounds__(256, 2)
gemm_logits_kernel(const float* __restrict__ Wy,
                   const float* __restrict__ Wyb,
                   float*       __restrict__ out)
{
    __shared__ float  As[BK][LDAS];
    __shared__ float2 Bs[BK][LDBS];          // each entry = (b, b)

    const int tid = threadIdx.x;
    const int tn  = tid & 15;
    const int tm  = tid >> 4;
    const int n0  = (int)blockIdx.x * 128;
    const int t0  = (int)blockIdx.y * 8;     // m0 = t0*16

    // A loader: [t][k][b] -> As[k][t_local*16+b] (verified R6/R9 loader)
    const int a_t = tid >> 5;                // 0..7
    const int a_k = (tid & 31) >> 1;         // 0..15
    const int a_b = (tid & 1) * 8;           // 0 or 8
    const float* Ag = g_hs + (size_t)(t0 + a_t) * (B_ * H_) + a_k * 16 + a_b;

    // B loader: row n = tid>>1, k-offset (tid&1)*8  (duplicated store)
    const int b_n = tid >> 1;
    const int b_k = (tid & 1) * 8;
    const float* Bg = Wy + (size_t)(n0 + b_n) * H_ + b_k;

    unsigned long long acc[4][8];            // [m-pair][n]
    #pragma unroll
    for (int i = 0; i < 4; i++)
        #pragma unroll
        for (int jj = 0; jj < 8; jj++) acc[i][jj] = 0ull;

    for (int k0 = 0; k0 < H_; k0 += BK) {
        float4 av0 = __ldg((const float4*)(Ag + (size_t)k0 * 16));
        float4 av1 = __ldg((const float4*)(Ag + (size_t)k0 * 16 + 4));
        float4 bv0 = __ldg((const float4*)(Bg + k0));
        float4 bv1 = __ldg((const float4*)(Bg + k0 + 4));
        __syncthreads();
        *(float4*)&As[a_k][a_t * 16 + a_b]     = av0;
        *(float4*)&As[a_k][a_t * 16 + a_b + 4] = av1;
        Bs[b_k + 0][b_n] = make_float2(bv0.x, bv0.x);
        Bs[b_k + 1][b_n] = make_float2(bv0.y, bv0.y);
        Bs[b_k + 2][b_n] = make_float2(bv0.z, bv0.z);
        Bs[b_k + 3][b_n] = make_float2(bv0.w, bv0.w);
        Bs[b_k + 4][b_n] = make_float2(bv1.x, bv1.x);
        Bs[b_k + 5][b_n] = make_float2(bv1.y, bv1.y);
        Bs[b_k + 6][b_n] = make_float2(bv1.z, bv1.z);
        Bs[b_k + 7][b_n] = make_float2(bv1.w, bv1.w);
        __syncthreads();

        #pragma unroll
        for (int k = 0; k < BK; k++) {
            // A pairs: (a0,a1),(a2,a3) per quad — direct LDS.128, no packs
            ulonglong2 aq0 = *(const ulonglong2*)&As[k][tm * 4];
            ulonglong2 aq1 = *(const ulonglong2*)&As[k][64 + tm * 4];
            unsigned long long am[4] = { aq0.x, aq0.y, aq1.x, aq1.y };
            // B duplicated pairs: (bn,bn) — direct LDS.128
            ulonglong2 bq0 = *(const ulonglong2*)&Bs[k][tn * 4];
            ulonglong2 bq1 = *(const ulonglong2*)&Bs[k][tn * 4 + 2];
            ulonglong2 bq2 = *(const ulonglong2*)&Bs[k][64 + tn * 4];
            ulonglong2 bq3 = *(const ulonglong2*)&Bs[k][64 + tn * 4 + 2];
            unsigned long long bn[8] = { bq0.x, bq0.y, bq1.x, bq1.y,
                                         bq2.x, bq2.y, bq3.x, bq3.y };
            #pragma unroll
            for (int i = 0; i < 4; i++)
                #pragma unroll
                for (int jj = 0; jj < 8; jj++)
                    fma2(acc[i][jj], am[i], bn[jj]);
        }
    }

    // ---- epilogue: bias + scatter to logits [b][t][v] ----
    float4 bias0 = __ldg((const float4*)(Wyb + n0 + tn * 4));
    float4 bias1 = __ldg((const float4*)(Wyb + n0 + 64 + tn * 4));
    #pragma unroll
    for (int i = 0; i < 4; i++) {
        // m-pair i covers m_tile base: quads {tm*4, 64+tm*4}, pair within quad
        int base = (i < 2) ? (tm * 4 + i * 2) : (64 + tm * 4 + (i - 2) * 2);
        float lo[8], hi[8];
        #pragma unroll
        for (int jj = 0; jj < 8; jj++) unpack2(acc[i][jj], lo[jj], hi[jj]);
        #pragma unroll
        for (int half = 0; half < 2; half++) {
            const float* f = half ? hi : lo;
            int m  = t0 * 16 + base + half;
            int tt = m >> 4;
            int bb = m & 15;
            float* orow = out + ((size_t)bb * T_ + tt) * V_ + n0;
            float4 v0 = make_float4(f[0] + bias0.x, f[1] + bias0.y,
                                    f[2] + bias0.z, f[3] + bias0.w);
            float4 v1 = make_float4(f[4] + bias1.x, f[5] + bias1.y,
                                    f[6] + bias1.z, f[7] + bias1.w);
            *(float4*)(orow + tn * 4)      = v0;
            *(float4*)(orow + 64 + tn * 4) = v1;
        }
    }
}

// ---------------------------------------------------------------------------
// Launch
// ---------------------------------------------------------------------------
extern "C" void kernel_launch(void* const* d_in, const int* in_sizes, int n_in,
                              void* d_out, int out_size) {
    const int*   x   = (const int*)  d_in[0];   // [B,T] int32
    const float* h0  = (const float*)d_in[1];   // [B,H]
    const float* Wx  = (const float*)d_in[2];   // [H,V]
    const float* Wxb = (const float*)d_in[3];   // [H]
    const float* Wh  = (const float*)d_in[4];   // [H,H]
    const float* Wy  = (const float*)d_in[5];   // [V,H]
    const float* Wyb = (const float*)d_in[6];   // [V]
    float* out = (float*)d_out;

    const int smem_rnn = (B_ * H_ + 8 * H_) * (int)sizeof(float);   // 96 KB
    cudaFuncSetAttribute(rnn_recurrence_kernel,
                         cudaFuncAttributeMaxDynamicSharedMemorySize, smem_rnn);
    rnn_recurrence_kernel<<<NBLK, 128, smem_rnn>>>(x, h0, Wx, Wxb, Wh,
                                                   out, out_size);

    dim3 grid(V_ / 128, (T_ * B_) / 128);   // (64, 128)
    gemm_logits_kernel<<<grid, 256>>>(Wy, Wyb, out);
}

// round 12
// speedup vs baseline: 1.3083x; 1.3083x over previous
#include <cuda_runtime.h>
#include <cstdint>

#define B_    16
#define T_    1024
#define V_    8192
#define H_    1024
#define NBLK  128
#define BTV   134217728   // B_*T_*V_

// ---------------------------------------------------------------------------
// Device-global scratch (allocation is forbidden) + grid-barrier state.
//   g_hs : [t][k][b] fp32 (GEMM A tiles; tile rows m = t*16+b)
//   g_hT : ping-pong h exchange in PAIR layout: idx = (j>>1)*32 + b*2 + (j&1)
//   barrier: two-level tree — 8 leaf counters (256B stride) x 16 arrivals,
//   then a root of 8; sense-reversing, counters return to 0 (replay-safe).
// ---------------------------------------------------------------------------
__device__ float    g_hs[(size_t)T_ * B_ * H_];   // 64 MB
__device__ float    g_hT[2][B_ * H_];
__device__ unsigned g_bar_leaf[8 * 64];           // leaf i at [i*64]
__device__ unsigned g_bar_root  = 0;
__device__ unsigned g_bar_sense = 0;

extern __shared__ float smem_dyn[];

// ---------------------------------------------------------------------------
// Packed f32x2 helpers (FFMA2 path: only reachable via PTX fma.rn.f32x2)
// ---------------------------------------------------------------------------
__device__ __forceinline__ unsigned long long pack2(float x, float y) {
    unsigned long long r;
    asm("mov.b64 %0, {%1, %2};" : "=l"(r) : "f"(x), "f"(y));
    return r;
}
__device__ __forceinline__ void fma2(unsigned long long &d,
                                     unsigned long long a,
                                     unsigned long long b) {
    asm("fma.rn.f32x2 %0, %1, %2, %0;" : "+l"(d) : "l"(a), "l"(b));
}
__device__ __forceinline__ void unpack2(unsigned long long v, float &lo, float &hi) {
    asm("mov.b64 {%0, %1}, %2;" : "=f"(lo), "=f"(hi) : "l"(v));
}

// ---------------------------------------------------------------------------
// Kernel 1: persistent RNN recurrence (exact verified R9 body; ONLY the
// grid barrier is replaced by the two-level tree).
//   h_t[b][j] = tanh( Wx_w[j, x[b,t]] + Wx_b[j] + sum_k h_{t-1}[b][k]*Wh[j][k] )
// 128 blocks x 128 threads; block owns 8 j, all 16 b.
// h held in PAIR layout [k/2][b][2] -> conflict-free LDS.64 + fma.f32x2.
// ---------------------------------------------------------------------------
__global__ void __launch_bounds__(128, 1)
rnn_recurrence_kernel(const int*   __restrict__ x,
                      const float* __restrict__ h0,
                      const float* __restrict__ Wx,
                      const float* __restrict__ Wxb,
                      const float* __restrict__ Wh,
                      float*       __restrict__ out,
                      int out_size)
{
    float* h_s  = smem_dyn;            // 16384 floats: h_{t-1} pair layout
    float* wh_s = smem_dyn + 16384;    //  8192 floats: Wh rows [jl][k]

    const int tid = threadIdx.x;
    const int j0  = (int)blockIdx.x * 8;
    const int jl  = tid >> 4;          // 0..7
    const int j   = j0 + jl;
    const int b   = tid & 15;

    {   // one-time: stage this block's 8 Wh rows (32 KB)
        const float4* src = (const float4*)(Wh + (size_t)j0 * H_);
        float4*       dst = (float4*)wh_s;
        #pragma unroll
        for (int s = 0; s < 16; s++)
            dst[tid + s * 128] = src[tid + s * 128];
    }

    const float  wxb   = Wxb[j];
    const float* wxrow = Wx + (size_t)j * V_;
    const int*   xrow  = x + b * T_;
    const float* whs   = wh_s + jl * H_;
    const int    pidx  = ((j >> 1) << 5) + (b << 1) + (j & 1);
    float*       hout  = g_hs + (size_t)j * 16 + b;    // [t][k][b], k = j

    for (int t = 0; t < T_; t++) {
        // ---- stage h_{t-1} into shared (pair layout) ----
        if (t == 0) {
            for (int i = tid; i < B_ * H_; i += 128) {
                int bb = (i >> 1) & 15;
                int kk = ((i >> 5) << 1) | (i & 1);
                h_s[i] = h0[bb * H_ + kk];
            }
        } else {
            const float4* src = (const float4*)(g_hT[(t - 1) & 1]);
            float4*       dst = (float4*)h_s;
            #pragma unroll
            for (int s = 0; s < 32; s++)
                dst[tid + s * 128] = __ldcg(src + tid + s * 128);
        }
        __syncthreads();

        // ---- embedding gather (L2-resident Wx) ----
        int   xi = __ldg(xrow + t);
        float e  = __ldg(wxrow + xi) + wxb;

        // ---- dot(h_{t-1}[b][:], Wh[j][:]) via f32x2, 8 chains ----
        unsigned long long acc2[8];
        #pragma unroll
        for (int i = 0; i < 8; i++) acc2[i] = 0ull;

        const char* hbase = (const char*)h_s + b * 8;
        #pragma unroll 2
        for (int kp = 0; kp < 512; kp += 8) {           // 16 k per iter
            ulonglong2 w01 = *(const ulonglong2*)(whs + 2 * kp);
            ulonglong2 w23 = *(const ulonglong2*)(whs + 2 * kp + 4);
            ulonglong2 w45 = *(const ulonglong2*)(whs + 2 * kp + 8);
            ulonglong2 w67 = *(const ulonglong2*)(whs + 2 * kp + 12);
            const char* hp = hbase + (size_t)kp * 128;
            fma2(acc2[0], *(const unsigned long long*)(hp + 0 * 128), w01.x);
            fma2(acc2[1], *(const unsigned long long*)(hp + 1 * 128), w01.y);
            fma2(acc2[2], *(const unsigned long long*)(hp + 2 * 128), w23.x);
            fma2(acc2[3], *(const unsigned long long*)(hp + 3 * 128), w23.y);
            fma2(acc2[4], *(const unsigned long long*)(hp + 4 * 128), w45.x);
            fma2(acc2[5], *(const unsigned long long*)(hp + 5 * 128), w45.y);
            fma2(acc2[6], *(const unsigned long long*)(hp + 6 * 128), w67.x);
            fma2(acc2[7], *(const unsigned long long*)(hp + 7 * 128), w67.y);
        }
        float dot;
        {
            float s0 = 0.f, s1 = 0.f;
            #pragma unroll
            for (int i = 0; i < 8; i += 2) {
                float l, h;
                unpack2(acc2[i], l, h);     s0 += l + h;
                unpack2(acc2[i + 1], l, h); s1 += l + h;
            }
            dot = s0 + s1;
        }
        float hv = tanhf(e + dot);

        // exchange buffer (pair layout; fully coalesced) + GEMM A matrix
        __stcg(&g_hT[t & 1][pidx], hv);
        __stcg(hout + (size_t)t * (B_ * H_), hv);

        if (t == T_ - 1 && out_size >= BTV + B_ * H_)
            out[(size_t)BTV + b * H_ + j] = hv;          // h_final [B][H]

        // ---- two-level grid barrier (sense-reversing, replay-safe) ----
        __threadfence();
        __syncthreads();
        if (tid == 0) {
            unsigned gen = *((volatile unsigned*)&g_bar_sense);
            unsigned* lc = &g_bar_leaf[((unsigned)blockIdx.x & 7u) * 64u];
            if (atomicAdd(lc, 1u) == 15u) {      // last of this leaf's 16
                atomicExch(lc, 0u);
                if (atomicAdd(&g_bar_root, 1u) == 7u) {   // last leaf
                    atomicExch(&g_bar_root, 0u);
                    __threadfence();
                    atomicAdd(&g_bar_sense, 1u);
                }
            }
            while (*((volatile unsigned*)&g_bar_sense) == gen) { }
        }
        __syncthreads();
        __threadfence();
    }
}

// ---------------------------------------------------------------------------
// Kernel 2: output GEMM (FFMA2) — exact verified R9 kernel (11515 us config).
//   logits[b][t][v] = sum_k hs[t][b][k] * Wy[v][k] + Wyb[v]
// A[m][k] = g_hs[t][k][b], m = t*16+b. 128x128x16 tiles, 256 threads.
// Thread (tm=tid>>4, tn=tid&15) owns m in {tm*4..+3, 64+tm*4..+3},
// n in {tn*4..+3, 64+tn*4..+3}: every LDS.128 spans a contiguous 256 B
// across the 16 lanes -> zero bank conflicts.
// ---------------------------------------------------------------------------
#define BK   16
#define LDAS 132   // 128 + pad 4

__global__ void __launch_bounds__(256)
gemm_logits_kernel(const float* __restrict__ Wy,
                   const float* __restrict__ Wyb,
                   float*       __restrict__ out)
{
    __shared__ float As[BK][LDAS];
    __shared__ float Bs[BK][LDAS];

    const int tid = threadIdx.x;
    const int tn  = tid & 15;
    const int tm  = tid >> 4;
    const int n0  = (int)blockIdx.x * 128;
    const int t0  = (int)blockIdx.y * 8;     // m0 = t0*16

    // A loader: [t][k][b] -> As[k][t_local*16+b] (verified R6 loader)
    const int a_t = tid >> 5;                // 0..7
    const int a_k = (tid & 31) >> 1;         // 0..15
    const int a_b = (tid & 1) * 8;           // 0 or 8
    const float* Ag = g_hs + (size_t)(t0 + a_t) * (B_ * H_) + a_k * 16 + a_b;

    // B loader: row n = tid>>1, k-offset (tid&1)*8
    const int b_n = tid >> 1;
    const int b_k = (tid & 1) * 8;
    const float* Bg = Wy + (size_t)(n0 + b_n) * H_ + b_k;

    unsigned long long acc[8][4];
    #pragma unroll
    for (int i = 0; i < 8; i++)
        #pragma unroll
        for (int jj = 0; jj < 4; jj++) acc[i][jj] = 0ull;

    for (int k0 = 0; k0 < H_; k0 += BK) {
        float4 av0 = __ldg((const float4*)(Ag + (size_t)k0 * 16));
        float4 av1 = __ldg((const float4*)(Ag + (size_t)k0 * 16 + 4));
        float4 bv0 = __ldg((const float4*)(Bg + k0));
        float4 bv1 = __ldg((const float4*)(Bg + k0 + 4));
        __syncthreads();
        *(float4*)&As[a_k][a_t * 16 + a_b]     = av0;
        *(float4*)&As[a_k][a_t * 16 + a_b + 4] = av1;
        Bs[b_k + 0][b_n] = bv0.x;  Bs[b_k + 1][b_n] = bv0.y;
        Bs[b_k + 2][b_n] = bv0.z;  Bs[b_k + 3][b_n] = bv0.w;
        Bs[b_k + 4][b_n] = bv1.x;  Bs[b_k + 5][b_n] = bv1.y;
        Bs[b_k + 6][b_n] = bv1.z;  Bs[b_k + 7][b_n] = bv1.w;
        __syncthreads();

        #pragma unroll
        for (int k = 0; k < BK; k++) {
            float4 aq0 = *(const float4*)&As[k][tm * 4];
            float4 aq1 = *(const float4*)&As[k][64 + tm * 4];
            ulonglong2 b01 = *(const ulonglong2*)&Bs[k][tn * 4];
            ulonglong2 b23 = *(const ulonglong2*)&Bs[k][64 + tn * 4];
            unsigned long long b2[4] = { b01.x, b01.y, b23.x, b23.y };
            float am[8] = { aq0.x, aq0.y, aq0.z, aq0.w,
                            aq1.x, aq1.y, aq1.z, aq1.w };
            #pragma unroll
            for (int i = 0; i < 8; i++) {
                unsigned long long a2 = pack2(am[i], am[i]);
                #pragma unroll
                for (int jj = 0; jj < 4; jj++) fma2(acc[i][jj], a2, b2[jj]);
            }
        }
    }

    // ---- epilogue: bias + scatter to logits [b][t][v] ----
    float4 bias0 = __ldg((const float4*)(Wyb + n0 + tn * 4));
    float4 bias1 = __ldg((const float4*)(Wyb + n0 + 64 + tn * 4));
    #pragma unroll
    for (int i = 0; i < 8; i++) {
        int m_tile = (i < 4) ? (tm * 4 + i) : (64 + tm * 4 + (i - 4));
        int m  = t0 * 16 + m_tile;
        int tt = m >> 4;
        int bb = m & 15;
        float* orow = out + ((size_t)bb * T_ + tt) * V_ + n0;
        float l0, h0v, l1, h1v;
        unpack2(acc[i][0], l0, h0v);
        unpack2(acc[i][1], l1, h1v);
        float4 v0 = make_float4(l0 + bias0.x, h0v + bias0.y,
                                l1 + bias0.z, h1v + bias0.w);
        *(float4*)(orow + tn * 4) = v0;
        unpack2(acc[i][2], l0, h0v);
        unpack2(acc[i][3], l1, h1v);
        float4 v1 = make_float4(l0 + bias1.x, h0v + bias1.y,
                                l1 + bias1.z, h1v + bias1.w);
        *(float4*)(orow + 64 + tn * 4) = v1;
    }
}

// ---------------------------------------------------------------------------
// Launch
// ---------------------------------------------------------------------------
extern "C" void kernel_launch(void* const* d_in, const int* in_sizes, int n_in,
                              void* d_out, int out_size) {
    const int*   x   = (const int*)  d_in[0];   // [B,T] int32
    const float* h0  = (const float*)d_in[1];   // [B,H]
    const float* Wx  = (const float*)d_in[2];   // [H,V]
    const float* Wxb = (const float*)d_in[3];   // [H]
    const float* Wh  = (const float*)d_in[4];   // [H,H]
    const float* Wy  = (const float*)d_in[5];   // [V,H]
    const float* Wyb = (const float*)d_in[6];   // [V]
    float* out = (float*)d_out;

    const int smem_rnn = (B_ * H_ + 8 * H_) * (int)sizeof(float);   // 96 KB
    cudaFuncSetAttribute(rnn_recurrence_kernel,
                         cudaFuncAttributeMaxDynamicSharedMemorySize, smem_rnn);
    rnn_recurrence_kernel<<<NBLK, 128, smem_rnn>>>(x, h0, Wx, Wxb, Wh,
                                                   out, out_size);

    dim3 grid(V_ / 128, (T_ * B_) / 128);   // (64, 128)
    gemm_logits_kernel<<<grid, 256>>>(Wy, Wyb, out);
}

// round 13
// speedup vs baseline: 1.5731x; 1.2024x over previous
#include <cuda_runtime.h>
#include <cstdint>

#define B_    16
#define T_    1024
#define V_    8192
#define H_    1024
#define NBLK  128
#define BTV   134217728   // B_*T_*V_

// ---------------------------------------------------------------------------
// Device-global scratch (allocation is forbidden) + grid-barrier state.
//   g_hs : [t][k][b] fp32 (GEMM A tiles; tile rows m = t*16+b)
//   g_hT : ping-pong h exchange in PAIR layout
//   g_bar_sense doubles as the producer progress counter (steps completed);
//   init_kernel zeroes all barrier state every launch (replay-safe).
// ---------------------------------------------------------------------------
__device__ float    g_hs[(size_t)T_ * B_ * H_];   // 64 MB
__device__ float    g_hT[2][B_ * H_];
__device__ unsigned g_bar_count;
__device__ unsigned g_bar_sense;

extern __shared__ float smem_dyn[];

#define BARSYNC(id) asm volatile("bar.sync %0, 128;" :: "r"(id) : "memory")

// ---------------------------------------------------------------------------
// Packed f32x2 helpers
// ---------------------------------------------------------------------------
__device__ __forceinline__ unsigned long long pack2(float x, float y) {
    unsigned long long r;
    asm("mov.b64 %0, {%1, %2};" : "=l"(r) : "f"(x), "f"(y));
    return r;
}
__device__ __forceinline__ void fma2(unsigned long long &d,
                                     unsigned long long a,
                                     unsigned long long b) {
    asm("fma.rn.f32x2 %0, %1, %2, %0;" : "+l"(d) : "l"(a), "l"(b));
}
__device__ __forceinline__ void unpack2(unsigned long long v, float &lo, float &hi) {
    asm("mov.b64 {%0, %1}, %2;" : "=f"(lo), "=f"(hi) : "l"(v));
}

__global__ void init_kernel() { g_bar_count = 0u; g_bar_sense = 0u; }

// ---------------------------------------------------------------------------
// Shared-memory layout (floats):
//   [0,16384)        h_s   : h_{t-1} pair layout
//   [16384,24576)    wh_s  : Wh rows of this block
//   [24576+g*3200)   group g GEMM buffers: As 16x132, Bs 16x68
// ---------------------------------------------------------------------------
#define SM_GEMM  24576
#define GRP_STR  3200
#define LDAS     132
#define LDBS     68
#define SMEM_FLOATS (SM_GEMM + 2 * GRP_STR)

// ---------------------------------------------------------------------------
// GEMM worker: processes 128x64 logits tiles (t-chunk mt, fixed n0 per block)
// pulled from a shared tile queue; per-tile gate on g_bar_sense >= mt*8+8.
// Core = verified R9 conflict-free interleaved-quad FFMA2 micro-tiles.
// ---------------------------------------------------------------------------
__device__ __forceinline__ void gemm_worker(
    int gtid, int bar_id, int grp,
    unsigned* s_tile, volatile unsigned* s_mt,
    int n0, const float* __restrict__ Wy, const float* __restrict__ Wyb,
    float* __restrict__ out)
{
    float* As = smem_dyn + SM_GEMM + grp * GRP_STR;          // [16][132]
    float* Bs = As + 16 * LDAS;                              // [16][68]

    const int tn = gtid & 7;
    const int tm = gtid >> 3;

    // A loader: 4 chunks c = gtid + q*128; bh=c&3, k=(c>>2)&15, tl=c>>6
    int a_bh[4], a_k[4], a_tl[4];
    #pragma unroll
    for (int q = 0; q < 4; q++) {
        int c = gtid + q * 128;
        a_bh[q] = c & 3; a_k[q] = (c >> 2) & 15; a_tl[q] = c >> 6;
    }
    // B loader: 2 chunks c = gtid + q*128; n=c>>2, kq=c&3
    int b_n[2], b_kq[2];
    #pragma unroll
    for (int q = 0; q < 2; q++) {
        int c = gtid + q * 128;
        b_n[q] = c >> 2; b_kq[q] = c & 3;
    }

    for (;;) {
        if (gtid == 0) s_mt[grp] = atomicAdd(s_tile, 1u);
        BARSYNC(bar_id);
        unsigned mt = s_mt[grp];
        BARSYNC(bar_id);
        if (mt >= 128u) break;
        const int t0 = (int)mt * 8;

        // gate: need all producer writes for t0..t0+7
        if (gtid == 0) {
            while (*((volatile unsigned*)&g_bar_sense) < (unsigned)(t0 + 8))
                __nanosleep(200);
        }
        BARSYNC(bar_id);

        unsigned long long acc[8][4];
        #pragma unroll
        for (int i = 0; i < 8; i++)
            #pragma unroll
            for (int jj = 0; jj < 4; jj++) acc[i][jj] = 0ull;

        for (int k0 = 0; k0 < H_; k0 += 16) {
            float4 av[4], bv[2];
            #pragma unroll
            for (int q = 0; q < 4; q++)
                av[q] = __ldcg((const float4*)(g_hs
                          + (size_t)(t0 + a_tl[q]) * (B_ * H_)
                          + (size_t)(k0 + a_k[q]) * 16 + a_bh[q] * 4));
            #pragma unroll
            for (int q = 0; q < 2; q++)
                bv[q] = __ldg((const float4*)(Wy
                          + (size_t)(n0 + b_n[q]) * H_ + k0 + b_kq[q] * 4));
            BARSYNC(bar_id);   // previous chunk's compute done
            #pragma unroll
            for (int q = 0; q < 4; q++)
                *(float4*)&As[a_k[q] * LDAS + a_tl[q] * 16 + a_bh[q] * 4] = av[q];
            #pragma unroll
            for (int q = 0; q < 2; q++) {
                Bs[(b_kq[q] * 4 + 0) * LDBS + b_n[q]] = bv[q].x;
                Bs[(b_kq[q] * 4 + 1) * LDBS + b_n[q]] = bv[q].y;
                Bs[(b_kq[q] * 4 + 2) * LDBS + b_n[q]] = bv[q].z;
                Bs[(b_kq[q] * 4 + 3) * LDBS + b_n[q]] = bv[q].w;
            }
            BARSYNC(bar_id);

            #pragma unroll
            for (int k = 0; k < 16; k++) {
                float4 aq0 = *(const float4*)&As[k * LDAS + tm * 4];
                float4 aq1 = *(const float4*)&As[k * LDAS + 64 + tm * 4];
                ulonglong2 b01 = *(const ulonglong2*)&Bs[k * LDBS + tn * 4];
                ulonglong2 b23 = *(const ulonglong2*)&Bs[k * LDBS + 32 + tn * 4];
                unsigned long long b2[4] = { b01.x, b01.y, b23.x, b23.y };
                float am[8] = { aq0.x, aq0.y, aq0.z, aq0.w,
                                aq1.x, aq1.y, aq1.z, aq1.w };
                #pragma unroll
                for (int i = 0; i < 8; i++) {
                    unsigned long long a2 = pack2(am[i], am[i]);
                    #pragma unroll
                    for (int jj = 0; jj < 4; jj++) fma2(acc[i][jj], a2, b2[jj]);
                }
            }
        }

        // epilogue: bias + scatter to logits [b][t][v]
        float4 bias0 = __ldg((const float4*)(Wyb + n0 + tn * 4));
        float4 bias1 = __ldg((const float4*)(Wyb + n0 + 32 + tn * 4));
        #pragma unroll
        for (int i = 0; i < 8; i++) {
            int m_tile = (i < 4) ? (tm * 4 + i) : (64 + tm * 4 + (i - 4));
            int m  = t0 * 16 + m_tile;
            int tt = m >> 4;
            int bb = m & 15;
            float* orow = out + ((size_t)bb * T_ + tt) * V_ + n0;
            float l0, h0v, l1, h1v;
            unpack2(acc[i][0], l0, h0v);
            unpack2(acc[i][1], l1, h1v);
            float4 v0 = make_float4(l0 + bias0.x, h0v + bias0.y,
                                    l1 + bias0.z, h1v + bias0.w);
            *(float4*)(orow + tn * 4) = v0;
            unpack2(acc[i][2], l0, h0v);
            unpack2(acc[i][3], l1, h1v);
            float4 v1 = make_float4(l0 + bias1.x, h0v + bias1.y,
                                    l1 + bias1.z, h1v + bias1.w);
            *(float4*)(orow + 32 + tn * 4) = v1;
        }
    }
}

// ---------------------------------------------------------------------------
// Fused persistent kernel. 128 blocks x 256 threads.
//   warps 0-3 : recurrence (verified R9 body, named barrier 1), then join GEMM
//   warps 4-7 : GEMM consumer from tile queue (named barrier 2)
// ---------------------------------------------------------------------------
__global__ void __launch_bounds__(256, 1)
fused_rnn_kernel(const int*   __restrict__ x,
                 const float* __restrict__ h0,
                 const float* __restrict__ Wx,
                 const float* __restrict__ Wxb,
                 const float* __restrict__ Wh,
                 const float* __restrict__ Wy,
                 const float* __restrict__ Wyb,
                 float*       __restrict__ out,
                 int out_size)
{
    __shared__ unsigned s_tile;
    __shared__ unsigned s_mt[2];

    const int tid = threadIdx.x;
    const int n0  = (int)blockIdx.x * 64;     // this block's GEMM n-column

    if (tid == 0) s_tile = 0u;
    asm volatile("bar.sync 0, 256;" ::: "memory");

    if (tid >= 128) {
        // -------- consumer group (warps 4-7) --------
        gemm_worker(tid - 128, 2, 1, &s_tile, s_mt, n0, Wy, Wyb, out);
        return;
    }

    // -------- producer group (warps 0-3): verified R9 recurrence --------
    float* h_s  = smem_dyn;            // 16384 floats: h_{t-1} pair layout
    float* wh_s = smem_dyn + 16384;    //  8192 floats: Wh rows [jl][k]

    const int j0  = (int)blockIdx.x * 8;
    const int jl  = tid >> 4;          // 0..7
    const int j   = j0 + jl;
    const int b   = tid & 15;

    {   // one-time: stage this block's 8 Wh rows (32 KB)
        const float4* src = (const float4*)(Wh + (size_t)j0 * H_);
        float4*       dst = (float4*)wh_s;
        #pragma unroll
        for (int s = 0; s < 16; s++)
            dst[tid + s * 128] = src[tid + s * 128];
    }

    const float  wxb   = Wxb[j];
    const float* wxrow = Wx + (size_t)j * V_;
    const int*   xrow  = x + b * T_;
    const float* whs   = wh_s + jl * H_;
    const int    pidx  = ((j >> 1) << 5) + (b << 1) + (j & 1);
    float*       hout  = g_hs + (size_t)j * 16 + b;    // [t][k][b], k = j

    for (int t = 0; t < T_; t++) {
        // ---- stage h_{t-1} into shared (pair layout) ----
        if (t == 0) {
            for (int i = tid; i < B_ * H_; i += 128) {
                int bb = (i >> 1) & 15;
                int kk = ((i >> 5) << 1) | (i & 1);
                h_s[i] = h0[bb * H_ + kk];
            }
        } else {
            const float4* src = (const float4*)(g_hT[(t - 1) & 1]);
            float4*       dst = (float4*)h_s;
            #pragma unroll
            for (int s = 0; s < 32; s++)
                dst[tid + s * 128] = __ldcg(src + tid + s * 128);
        }
        BARSYNC(1);

        // ---- embedding gather (L2-resident Wx) ----
        int   xi = __ldg(xrow + t);
        float e  = __ldg(wxrow + xi) + wxb;

        // ---- dot(h_{t-1}[b][:], Wh[j][:]) via f32x2, 8 chains ----
        unsigned long long acc2[8];
        #pragma unroll
        for (int i = 0; i < 8; i++) acc2[i] = 0ull;

        const char* hbase = (const char*)h_s + b * 8;
        #pragma unroll 2
        for (int kp = 0; kp < 512; kp += 8) {           // 16 k per iter
            ulonglong2 w01 = *(const ulonglong2*)(whs + 2 * kp);
            ulonglong2 w23 = *(const ulonglong2*)(whs + 2 * kp + 4);
            ulonglong2 w45 = *(const ulonglong2*)(whs + 2 * kp + 8);
            ulonglong2 w67 = *(const ulonglong2*)(whs + 2 * kp + 12);
            const char* hp = hbase + (size_t)kp * 128;
            fma2(acc2[0], *(const unsigned long long*)(hp + 0 * 128), w01.x);
            fma2(acc2[1], *(const unsigned long long*)(hp + 1 * 128), w01.y);
            fma2(acc2[2], *(const unsigned long long*)(hp + 2 * 128), w23.x);
            fma2(acc2[3], *(const unsigned long long*)(hp + 3 * 128), w23.y);
            fma2(acc2[4], *(const unsigned long long*)(hp + 4 * 128), w45.x);
            fma2(acc2[5], *(const unsigned long long*)(hp + 5 * 128), w45.y);
            fma2(acc2[6], *(const unsigned long long*)(hp + 6 * 128), w67.x);
            fma2(acc2[7], *(const unsigned long long*)(hp + 7 * 128), w67.y);
        }
        float dot;
        {
            float s0 = 0.f, s1 = 0.f;
            #pragma unroll
            for (int i = 0; i < 8; i += 2) {
                float l, h;
                unpack2(acc2[i], l, h);     s0 += l + h;
                unpack2(acc2[i + 1], l, h); s1 += l + h;
            }
            dot = s0 + s1;
        }
        float hv = tanhf(e + dot);

        // exchange buffer (pair layout) + GEMM A matrix
        __stcg(&g_hT[t & 1][pidx], hv);
        __stcg(hout + (size_t)t * (B_ * H_), hv);

        if (t == T_ - 1 && out_size >= BTV + B_ * H_)
            out[(size_t)BTV + b * H_ + j] = hv;          // h_final [B][H]

        // ---- flat grid barrier (sense = steps completed; replay-safe via init) ----
        __threadfence();
        BARSYNC(1);
        if (tid == 0) {
            unsigned gen = *((volatile unsigned*)&g_bar_sense);
            unsigned arr = atomicAdd(&g_bar_count, 1u);
            if (arr == NBLK - 1) {
                atomicExch(&g_bar_count, 0u);
                __threadfence();
                atomicAdd(&g_bar_sense, 1u);
            } else {
                while (*((volatile unsigned*)&g_bar_sense) == gen) { }
            }
        }
        BARSYNC(1);
        __threadfence();
    }

    // -------- producer done: join the GEMM as group 0 --------
    gemm_worker(tid, 1, 0, &s_tile, s_mt, n0, Wy, Wyb, out);
}

// ---------------------------------------------------------------------------
// Launch
// ---------------------------------------------------------------------------
extern "C" void kernel_launch(void* const* d_in, const int* in_sizes, int n_in,
                              void* d_out, int out_size) {
    const int*   x   = (const int*)  d_in[0];   // [B,T] int32
    const float* h0  = (const float*)d_in[1];   // [B,H]
    const float* Wx  = (const float*)d_in[2];   // [H,V]
    const float* Wxb = (const float*)d_in[3];   // [H]
    const float* Wh  = (const float*)d_in[4];   // [H,H]
    const float* Wy  = (const float*)d_in[5];   // [V,H]
    const float* Wyb = (const float*)d_in[6];   // [V]
    float* out = (float*)d_out;

    init_kernel<<<1, 1>>>();

    const int smem = SMEM_FLOATS * (int)sizeof(float);   // ~121 KB
    cudaFuncSetAttribute(fused_rnn_kernel,
                         cudaFuncAttributeMaxDynamicSharedMemorySize, smem);
    fused_rnn_kernel<<<NBLK, 256, smem>>>(x, h0, Wx, Wxb, Wh, Wy, Wyb,
                                          out, out_size);
}